// round 7
// baseline (speedup 1.0000x reference)
#include <cuda_runtime.h>
#include <cuda_fp16.h>
#include <math.h>
#include <stdint.h>

#define Bc    2
#define Tc    2048
#define Ec    2048
#define Hc    16
#define HKVc  4
#define Mc    4
#define HDc   32
#define BTc   (Bc*Tc)      // 4096
#define KVE   512

// ---------------- scratch (device globals; no allocations allowed) ----------
__device__ float g_q[(size_t)BTc * Ec];     // Q proj fp32 (B,T,64,32)
__device__ float g_k[(size_t)BTc * KVE];    // K proj fp32 (B,T,16,32)
__device__ float g_v[(size_t)BTc * KVE];    // V proj fp32 (B,T,4,128)

// fp16 2-limb planes (limb p at offset p*plane)
__device__ __align__(16) __half g_x2[(size_t)2 * BTc * Ec];   // x / normed-combined
__device__ __align__(16) __half g_q2[(size_t)2 * BTc * Ec];   // rotated Q
__device__ __align__(16) __half g_k2[(size_t)2 * BTc * KVE];  // rotated K
__device__ __align__(16) __half g_v2[(size_t)2 * BTc * KVE];  // V
__device__ __align__(16) __half g_wq2[(size_t)2 * Ec * Ec];
__device__ __align__(16) __half g_wk2[(size_t)2 * KVE * Ec];
__device__ __align__(16) __half g_wv2[(size_t)2 * KVE * Ec];
__device__ __align__(16) __half g_wo2[(size_t)2 * Ec * Ec];

// ================= PTX helpers =================
__device__ __forceinline__ uint32_t smem_u32(const void* p) {
    uint32_t a;
    asm("{ .reg .u64 t; cvta.to.shared.u64 t, %1; cvt.u32.u64 %0, t; }"
        : "=r"(a) : "l"(p));
    return a;
}
#define LDSM_X4(r, addr)                                                       \
    asm volatile("ldmatrix.sync.aligned.m8n8.x4.shared.b16 {%0,%1,%2,%3}, [%4];" \
        : "=r"((r)[0]), "=r"((r)[1]), "=r"((r)[2]), "=r"((r)[3]) : "r"(addr))
#define LDSM_X4T(r, addr)                                                      \
    asm volatile("ldmatrix.sync.aligned.m8n8.x4.trans.shared.b16 {%0,%1,%2,%3}, [%4];" \
        : "=r"((r)[0]), "=r"((r)[1]), "=r"((r)[2]), "=r"((r)[3]) : "r"(addr))
#define MMA16816(D, A, b0, b1)                                                 \
    asm volatile("mma.sync.aligned.m16n8k16.row.col.f32.f16.f16.f32 "          \
        "{%0,%1,%2,%3},{%4,%5,%6,%7},{%8,%9},{%0,%1,%2,%3};"                   \
        : "+f"((D)[0]), "+f"((D)[1]), "+f"((D)[2]), "+f"((D)[3])               \
        : "r"((A)[0]), "r"((A)[1]), "r"((A)[2]), "r"((A)[3]), "r"(b0), "r"(b1))
#define CP_ASYNC16(saddr, gaddr)                                               \
    asm volatile("cp.async.cg.shared.global [%0], [%1], 16;"                   \
        :: "r"(saddr), "l"(gaddr) : "memory")
#define CP_COMMIT()  asm volatile("cp.async.commit_group;" ::: "memory")
#define CP_WAIT1()   asm volatile("cp.async.wait_group 1;" ::: "memory")
#define CP_WAIT0()   asm volatile("cp.async.wait_group 0;" ::: "memory")

// =====================================================================
// split2: fp32 -> 2 fp16 limbs (h, l)
// =====================================================================
__global__ void split2_kernel(const float* __restrict__ src,
                              __half* __restrict__ dst,
                              size_t n2, size_t plane)
{
    size_t i = (size_t)blockIdx.x * blockDim.x + threadIdx.x;
    if (i >= n2) return;
    float2 v = *(const float2*)(src + i * 2);
    __half h0 = __float2half_rn(v.x);
    __half h1 = __float2half_rn(v.y);
    __half l0 = __float2half_rn(v.x - __half2float(h0));
    __half l1 = __float2half_rn(v.y - __half2float(h1));
    *(__half2*)(dst + i * 2)         = __halves2half2(h0, h1);
    *(__half2*)(dst + plane + i * 2) = __halves2half2(l0, l1);
}

// =====================================================================
// fp16 3-pass HMMA GEMM (verified in R5)
// =====================================================================
#define GBK      64
#define PLANE_B  16384
#define STAGE_B  (4 * PLANE_B)
#define G_SMEM   (2 * STAGE_B)

__global__ __launch_bounds__(256) void hgemm3(
    const __half* __restrict__ A2, size_t aplane,
    const __half* __restrict__ Wa2, float* __restrict__ Ca,
    const __half* __restrict__ Wb2, float* __restrict__ Cb,
    int N, int K)
{
    const __half* W2 = blockIdx.z ? Wb2 : Wa2;
    float*        C  = blockIdx.z ? Cb  : Ca;
    const size_t wplane = (size_t)N * K;

    extern __shared__ char smem[];
    const uint32_t sb = smem_u32(smem);
    const int tid  = threadIdx.x;
    const int lane = tid & 31;
    const int warp = tid >> 5;
    const int wm   = warp & 3;
    const int wn   = warp >> 2;
    const int row0 = blockIdx.y * 128;
    const int col0 = blockIdx.x * 128;

    const int lrow = tid >> 1;
    const int ucb  = (tid & 1) * 4;
    const __half* srcs[4] = {
        A2 +            (size_t)(row0 + lrow) * K,
        A2 + aplane   + (size_t)(row0 + lrow) * K,
        W2 +            (size_t)(col0 + lrow) * K,
        W2 + wplane   + (size_t)(col0 + lrow) * K };
    uint32_t dsts[4][4];
#pragma unroll
    for (int p = 0; p < 4; p++)
#pragma unroll
        for (int j = 0; j < 4; j++) {
            uint32_t off = (uint32_t)lrow * 128 + (ucb + j) * 16;
            dsts[p][j] = p * PLANE_B + (off ^ ((off >> 3) & 0x70));
        }

    float d[2][8][4];
#pragma unroll
    for (int f = 0; f < 2; f++)
#pragma unroll
        for (int g = 0; g < 8; g++)
#pragma unroll
            for (int e = 0; e < 4; e++) d[f][g][e] = 0.f;

    const int l7  = lane & 7;
    const int am  = wm * 32 + l7 + ((lane >> 3) & 1) * 8;
    const int aku = (lane >> 4) & 1;
    const int bn  = wn * 64 + ((lane >> 4) << 3) + l7;
    const int bku = (lane >> 3) & 1;

    const int nkt = K / GBK;

    {
        const uint32_t base = sb;
#pragma unroll
        for (int p = 0; p < 4; p++)
#pragma unroll
            for (int j = 0; j < 4; j++)
                CP_ASYNC16(base + dsts[p][j], srcs[p] + (ucb + j) * 8);
        CP_COMMIT();
    }

    for (int kt = 0; kt < nkt; kt++) {
        if (kt + 1 < nkt) {
            const uint32_t base = sb + ((kt + 1) & 1) * STAGE_B;
            const int ko = (kt + 1) * GBK;
#pragma unroll
            for (int p = 0; p < 4; p++)
#pragma unroll
                for (int j = 0; j < 4; j++)
                    CP_ASYNC16(base + dsts[p][j], srcs[p] + ko + (ucb + j) * 8);
            CP_COMMIT();
            CP_WAIT1();
        } else {
            CP_WAIT0();
        }
        __syncthreads();

        const uint32_t ab  = sb + (kt & 1) * STAGE_B;
        const uint32_t alb = ab + PLANE_B;
        const uint32_t wb  = ab + 2 * PLANE_B;
        const uint32_t wlb = ab + 3 * PLANE_B;

#pragma unroll
        for (int kk = 0; kk < 4; kk++) {
            uint32_t a0[4], a1[4], q0[4], q1[4];
            const uint32_t kxa = (uint32_t)(((kk * 2 + aku) ^ l7) * 16);
            LDSM_X4(a0, ab  +  am       * 128 + kxa);
            LDSM_X4(a1, ab  + (am + 16) * 128 + kxa);
            LDSM_X4(q0, alb +  am       * 128 + kxa);
            LDSM_X4(q1, alb + (am + 16) * 128 + kxa);
            const uint32_t kxb = (uint32_t)(((kk * 2 + bku) ^ l7) * 16);
#pragma unroll
            for (int p = 0; p < 4; p++) {
                uint32_t bh[4], bl[4];
                LDSM_X4(bh, wb  + (bn + p * 16) * 128 + kxb);
                LDSM_X4(bl, wlb + (bn + p * 16) * 128 + kxb);
                MMA16816(d[0][2*p],     a0, bh[0], bh[1]);
                MMA16816(d[0][2*p],     a0, bl[0], bl[1]);
                MMA16816(d[0][2*p],     q0, bh[0], bh[1]);
                MMA16816(d[0][2*p + 1], a0, bh[2], bh[3]);
                MMA16816(d[0][2*p + 1], a0, bl[2], bl[3]);
                MMA16816(d[0][2*p + 1], q0, bh[2], bh[3]);
                MMA16816(d[1][2*p],     a1, bh[0], bh[1]);
                MMA16816(d[1][2*p],     a1, bl[0], bl[1]);
                MMA16816(d[1][2*p],     q1, bh[0], bh[1]);
                MMA16816(d[1][2*p + 1], a1, bh[2], bh[3]);
                MMA16816(d[1][2*p + 1], a1, bl[2], bl[3]);
                MMA16816(d[1][2*p + 1], q1, bh[2], bh[3]);
            }
        }
        __syncthreads();
    }

    const int grp  = lane >> 2;
    const int tig2 = (lane & 3) * 2;
#pragma unroll
    for (int f = 0; f < 2; f++) {
        const int row = row0 + wm * 32 + f * 16 + grp;
#pragma unroll
        for (int g = 0; g < 8; g++) {
            const int col = col0 + wn * 64 + g * 8 + tig2;
            *(float2*)(C + (size_t)row * N + col) =
                make_float2(d[f][g][0], d[f][g][1]);
            *(float2*)(C + (size_t)(row + 8) * N + col) =
                make_float2(d[f][g][2], d[f][g][3]);
        }
    }
}

// =====================================================================
// RoPE + fp16 2-limb split
// =====================================================================
__global__ void rope_split_kernel(const float* __restrict__ src,
                                  __half* __restrict__ dst, size_t plane,
                                  const float* __restrict__ cs,
                                  const float* __restrict__ sn, int nh)
{
    int idx = blockIdx.x * 256 + threadIdx.x;
    int total = BTc * nh * (HDc / 2);
    if (idx >= total) return;
    int p    = idx & (HDc / 2 - 1);
    int rest = idx >> 4;
    int hh   = rest % nh;
    int row  = rest / nh;
    int t    = row & (Tc - 1);
    float c = cs[t * (HDc / 2) + p];
    float s = sn[t * (HDc / 2) + p];
    const float* ptr = src + ((size_t)row * nh + hh) * HDc + 2 * p;
    float x1 = ptr[0], x2 = ptr[1];
    float o1 = x1 * c - x2 * s;
    float o2 = x1 * s + x2 * c;
    __half h0 = __float2half_rn(o1);
    __half h1 = __float2half_rn(o2);
    __half l0 = __float2half_rn(o1 - __half2float(h0));
    __half l1 = __float2half_rn(o2 - __half2float(h1));
    size_t base = ((size_t)row * nh + hh) * HDc + 2 * p;
    *(__half2*)(dst + base)         = __halves2half2(h0, h1);
    *(__half2*)(dst + plane + base) = __halves2half2(l0, l1);
}

// =====================================================================
// Tensor-core fused 4-ensemble flash attention + RMSNorm.
// Block = (64 q-rows, h, b), 256 threads = 8 warps (rb = warp&3 row band,
// ch = warp>>2 column half). All GEMMs: 3-pass fp16 2-limb m16n8k16.
// =====================================================================
#define SQH   0
#define SQL   20480
#define SKH   40960
#define SKL   61440
#define SVH   81920
#define SVL   99328
#define SPH   116736
#define SPL   125952
#define SSTM  135168
#define SSTI  136192
#define SRED1 137216
#define SRED2 139264
#define FLM_SMEM 141312

__global__ __launch_bounds__(256, 1) void flash_mma(
    const __half* __restrict__ Q2, const __half* __restrict__ K2,
    const __half* __restrict__ V2, const float* __restrict__ rawmap,
    const float* __restrict__ wscale, const float* __restrict__ gamma,
    __half* __restrict__ Out2)
{
    extern __shared__ char sm[];
    const uint32_t sb = smem_u32(sm);
    float* fsm = (float*)sm;

    const int qt  = gridDim.x - 1 - blockIdx.x;
    const int h   = blockIdx.y;
    const int b   = blockIdx.z;
    const int hkv = h >> 2;
    const int tid = threadIdx.x;
    const int lane = tid & 31;
    const int warp = tid >> 5;
    const int rb  = warp & 3;
    const int ch  = warp >> 2;
    const int q0  = qt * 64;
    const float scale = 0.17677669529663687f;

    const size_t qpl = (size_t)BTc * Ec;
    const size_t kpl = (size_t)BTc * KVE;

    const int r1  = rb * 16 + (lane >> 2);
    const int bg  = lane >> 3;
    const int l7  = lane & 7;
    const int l15 = lane & 15;
    const int lc  = lane >> 4;
    const int l3  = lane & 3;

    // ---- load Q tiles (4 m, 2 limbs) ----
#pragma unroll
    for (int u = 0; u < 8; u++) {
        int idx  = u * 256 + tid;
        int limb = idx >> 10;
        int rest = idx & 1023;
        int m  = rest >> 8;
        int r  = (rest >> 2) & 63;
        int c  = rest & 3;
        const __half* src = Q2 + (size_t)limb * qpl
            + ((size_t)(b * Tc + q0 + r) * 64 + h * 4 + m) * HDc + c * 8;
        CP_ASYNC16(sb + SQH + limb * 20480 + (m * 64 + r) * 80 + c * 16, src);
    }
    CP_COMMIT();

    float mapw[4];
#pragma unroll
    for (int m = 0; m < 4; m++) mapw[m] = tanhf(rawmap[m]) * wscale[0];

    float RM[4][2], RS[4][2];
#pragma unroll
    for (int m = 0; m < 4; m++) {
        RM[m][0] = RM[m][1] = -1e30f;
        RS[m][0] = RS[m][1] = 0.f;
    }

    // ======================= PASS 1: softmax stats =======================
    for (int jt = 0; jt <= qt; jt++) {
        const int k0 = jt * 64;
        __syncthreads();
#pragma unroll
        for (int u = 0; u < 8; u++) {
            int idx  = u * 256 + tid;
            int limb = idx >> 10;
            int rest = idx & 1023;
            int m  = rest >> 8;
            int r  = (rest >> 2) & 63;
            int c  = rest & 3;
            const __half* src = K2 + (size_t)limb * kpl
                + ((size_t)(b * Tc + k0 + r) * 16 + hkv * 4 + m) * HDc + c * 8;
            CP_ASYNC16(sb + SKH + limb * 20480 + (m * 64 + r) * 80 + c * 16, src);
        }
        CP_COMMIT(); CP_WAIT0();
        __syncthreads();

        const bool diag = (jt == qt);
        float S[4][4][4];
#pragma unroll
        for (int m = 0; m < 4; m++) {
#pragma unroll
            for (int nf = 0; nf < 4; nf++)
#pragma unroll
                for (int e = 0; e < 4; e++) S[m][nf][e] = 0.f;
            uint32_t Ah[2][4], Al[2][4];
#pragma unroll
            for (int kf = 0; kf < 2; kf++) {
                uint32_t a = sb + SQH + (m * 64 + rb * 16 + l15) * 80 + lc * 16 + kf * 32;
                LDSM_X4(Ah[kf], a);
                LDSM_X4(Al[kf], a + 20480);
            }
#pragma unroll
            for (int np = 0; np < 2; np++) {
                uint32_t Bh[2][4], Bl[2][4];
#pragma unroll
                for (int kf = 0; kf < 2; kf++) {
                    uint32_t a = sb + SKH
                        + (m * 64 + ch * 32 + np * 16 + (bg >> 1) * 8 + l7) * 80
                        + kf * 32 + (bg & 1) * 16;
                    LDSM_X4(Bh[kf], a);
                    LDSM_X4(Bl[kf], a + 20480);
                }
#pragma unroll
                for (int kf = 0; kf < 2; kf++) {
                    MMA16816(S[m][np*2],   Ah[kf], Bh[kf][0], Bh[kf][1]);
                    MMA16816(S[m][np*2],   Al[kf], Bh[kf][0], Bh[kf][1]);
                    MMA16816(S[m][np*2],   Ah[kf], Bl[kf][0], Bl[kf][1]);
                    MMA16816(S[m][np*2+1], Ah[kf], Bh[kf][2], Bh[kf][3]);
                    MMA16816(S[m][np*2+1], Al[kf], Bh[kf][2], Bh[kf][3]);
                    MMA16816(S[m][np*2+1], Ah[kf], Bl[kf][2], Bl[kf][3]);
                }
            }
        }
        // scale + causal mask
#pragma unroll
        for (int m = 0; m < 4; m++)
#pragma unroll
            for (int nf = 0; nf < 4; nf++)
#pragma unroll
                for (int e = 0; e < 4; e++) {
                    int row = r1 + (e >> 1) * 8;
                    int col = ch * 32 + nf * 8 + l3 * 2 + (e & 1);
                    float s = S[m][nf][e] * scale;
                    if (diag && (k0 + col > q0 + row)) s = -1e30f;
                    S[m][nf][e] = s;
                }
        // tile row-max: quad reduce + cross-warp (2 col halves) via smem
#pragma unroll
        for (int m = 0; m < 4; m++) {
            float t1 = fmaxf(fmaxf(S[m][0][0], S[m][0][1]), fmaxf(S[m][1][0], S[m][1][1]));
            t1 = fmaxf(t1, fmaxf(fmaxf(S[m][2][0], S[m][2][1]), fmaxf(S[m][3][0], S[m][3][1])));
            float t2 = fmaxf(fmaxf(S[m][0][2], S[m][0][3]), fmaxf(S[m][1][2], S[m][1][3]));
            t2 = fmaxf(t2, fmaxf(fmaxf(S[m][2][2], S[m][2][3]), fmaxf(S[m][3][2], S[m][3][3])));
#pragma unroll
            for (int o = 1; o < 4; o <<= 1) {
                t1 = fmaxf(t1, __shfl_xor_sync(0xffffffffu, t1, o));
                t2 = fmaxf(t2, __shfl_xor_sync(0xffffffffu, t2, o));
            }
            if (l3 == 0) {
                fsm[SRED1/4 + (m * 64 + r1) * 2 + ch]     = t1;
                fsm[SRED1/4 + (m * 64 + r1 + 8) * 2 + ch] = t2;
            }
        }
        __syncthreads();
        // new max MN (kept separate from RM), p-sums with MN
        float MN[4][2];
#pragma unroll
        for (int m = 0; m < 4; m++) {
            MN[m][0] = fmaxf(RM[m][0], fmaxf(fsm[SRED1/4 + (m*64 + r1)*2],
                                             fsm[SRED1/4 + (m*64 + r1)*2 + 1]));
            MN[m][1] = fmaxf(RM[m][1], fmaxf(fsm[SRED1/4 + (m*64 + r1 + 8)*2],
                                             fsm[SRED1/4 + (m*64 + r1 + 8)*2 + 1]));
            float p1 = 0.f, p2 = 0.f;
#pragma unroll
            for (int nf = 0; nf < 4; nf++) {
                p1 += __expf(S[m][nf][0] - MN[m][0]) + __expf(S[m][nf][1] - MN[m][0]);
                p2 += __expf(S[m][nf][2] - MN[m][1]) + __expf(S[m][nf][3] - MN[m][1]);
            }
#pragma unroll
            for (int o = 1; o < 4; o <<= 1) {
                p1 += __shfl_xor_sync(0xffffffffu, p1, o);
                p2 += __shfl_xor_sync(0xffffffffu, p2, o);
            }
            if (l3 == 0) {
                fsm[SRED2/4 + (m * 64 + r1) * 2 + ch]     = p1;
                fsm[SRED2/4 + (m * 64 + r1 + 8) * 2 + ch] = p2;
            }
        }
        __syncthreads();
        // online update with correction factor exp(RM_old - MN)
#pragma unroll
        for (int m = 0; m < 4; m++) {
            float p1 = fsm[SRED2/4 + (m*64 + r1)*2] + fsm[SRED2/4 + (m*64 + r1)*2 + 1];
            float p2 = fsm[SRED2/4 + (m*64 + r1 + 8)*2] + fsm[SRED2/4 + (m*64 + r1 + 8)*2 + 1];
            RS[m][0] = RS[m][0] * __expf(RM[m][0] - MN[m][0]) + p1;
            RS[m][1] = RS[m][1] * __expf(RM[m][1] - MN[m][1]) + p2;
            RM[m][0] = MN[m][0];
            RM[m][1] = MN[m][1];
        }
    }

    // final stats to smem (every (row,m) written by ch==0, l3==0 owner)
    if (l3 == 0 && ch == 0) {
#pragma unroll
        for (int m = 0; m < 4; m++) {
            fsm[SSTM/4 + m * 64 + r1]     = RM[m][0];
            fsm[SSTM/4 + m * 64 + r1 + 8] = RM[m][1];
            fsm[SSTI/4 + m * 64 + r1]     = mapw[m] / RS[m][0];
            fsm[SSTI/4 + m * 64 + r1 + 8] = mapw[m] / RS[m][1];
        }
    }
    __syncthreads();

    float SMv[4][2], SIv[4][2];
#pragma unroll
    for (int m = 0; m < 4; m++) {
        SMv[m][0] = fsm[SSTM/4 + m * 64 + r1];
        SMv[m][1] = fsm[SSTM/4 + m * 64 + r1 + 8];
        SIv[m][0] = fsm[SSTI/4 + m * 64 + r1];
        SIv[m][1] = fsm[SSTI/4 + m * 64 + r1 + 8];
    }

    // ======================= PASS 2: combined P + PV =======================
    float acc[8][4];
#pragma unroll
    for (int nf = 0; nf < 8; nf++)
#pragma unroll
        for (int e = 0; e < 4; e++) acc[nf][e] = 0.f;

    for (int jt = 0; jt <= qt; jt++) {
        const int k0 = jt * 64;
        __syncthreads();
#pragma unroll
        for (int u = 0; u < 8; u++) {
            int idx  = u * 256 + tid;
            int limb = idx >> 10;
            int rest = idx & 1023;
            int m  = rest >> 8;
            int r  = (rest >> 2) & 63;
            int c  = rest & 3;
            const __half* src = K2 + (size_t)limb * kpl
                + ((size_t)(b * Tc + k0 + r) * 16 + hkv * 4 + m) * HDc + c * 8;
            CP_ASYNC16(sb + SKH + limb * 20480 + (m * 64 + r) * 80 + c * 16, src);
        }
#pragma unroll
        for (int u = 0; u < 8; u++) {
            int idx  = u * 256 + tid;
            int limb = idx >> 10;
            int rest = idx & 1023;
            int r  = (rest >> 4) & 63;
            int c  = rest & 15;
            const __half* src = V2 + (size_t)limb * kpl
                + ((size_t)(b * Tc + k0 + r) * 4 + hkv) * 128 + c * 8;
            CP_ASYNC16(sb + SVH + limb * 17408 + r * 272 + c * 16, src);
        }
        CP_COMMIT(); CP_WAIT0();
        __syncthreads();

        const bool diag = (jt == qt);
        float Pa[4][4];
#pragma unroll
        for (int nf = 0; nf < 4; nf++)
#pragma unroll
            for (int e = 0; e < 4; e++) Pa[nf][e] = 0.f;

#pragma unroll
        for (int m = 0; m < 4; m++) {
            float S[4][4];
#pragma unroll
            for (int nf = 0; nf < 4; nf++)
#pragma unroll
                for (int e = 0; e < 4; e++) S[nf][e] = 0.f;
            uint32_t Ah[2][4], Al[2][4];
#pragma unroll
            for (int kf = 0; kf < 2; kf++) {
                uint32_t a = sb + SQH + (m * 64 + rb * 16 + l15) * 80 + lc * 16 + kf * 32;
                LDSM_X4(Ah[kf], a);
                LDSM_X4(Al[kf], a + 20480);
            }
#pragma unroll
            for (int np = 0; np < 2; np++) {
                uint32_t Bh[2][4], Bl[2][4];
#pragma unroll
                for (int kf = 0; kf < 2; kf++) {
                    uint32_t a = sb + SKH
                        + (m * 64 + ch * 32 + np * 16 + (bg >> 1) * 8 + l7) * 80
                        + kf * 32 + (bg & 1) * 16;
                    LDSM_X4(Bh[kf], a);
                    LDSM_X4(Bl[kf], a + 20480);
                }
#pragma unroll
                for (int kf = 0; kf < 2; kf++) {
                    MMA16816(S[np*2],   Ah[kf], Bh[kf][0], Bh[kf][1]);
                    MMA16816(S[np*2],   Al[kf], Bh[kf][0], Bh[kf][1]);
                    MMA16816(S[np*2],   Ah[kf], Bl[kf][0], Bl[kf][1]);
                    MMA16816(S[np*2+1], Ah[kf], Bh[kf][2], Bh[kf][3]);
                    MMA16816(S[np*2+1], Al[kf], Bh[kf][2], Bh[kf][3]);
                    MMA16816(S[np*2+1], Ah[kf], Bl[kf][2], Bl[kf][3]);
                }
            }
#pragma unroll
            for (int nf = 0; nf < 4; nf++)
#pragma unroll
                for (int e = 0; e < 4; e++) {
                    int row = r1 + (e >> 1) * 8;
                    int col = ch * 32 + nf * 8 + l3 * 2 + (e & 1);
                    float s = S[nf][e] * scale;
                    if (diag && (k0 + col > q0 + row)) s = -1e30f;
                    int hf = e >> 1;
                    Pa[nf][e] += SIv[m][hf] * __expf(s - SMv[m][hf]);
                }
        }
        // store combined P (x256) as fp16 limbs
#pragma unroll
        for (int nf = 0; nf < 4; nf++) {
            int colb = (ch * 32 + nf * 8 + l3 * 2) * 2;
#pragma unroll
            for (int hh = 0; hh < 2; hh++) {
                float v0 = Pa[nf][hh*2]     * 256.f;
                float v1 = Pa[nf][hh*2 + 1] * 256.f;
                __half h0 = __float2half_rn(v0);
                __half h1 = __float2half_rn(v1);
                __half l0 = __float2half_rn(v0 - __half2float(h0));
                __half l1 = __float2half_rn(v1 - __half2float(h1));
                uint32_t off = (uint32_t)(r1 + hh * 8) * 144 + colb;
                *(__half2*)(sm + SPH + off) = __halves2half2(h0, h1);
                *(__half2*)(sm + SPL + off) = __halves2half2(l0, l1);
            }
        }
        __syncthreads();

        // PV: acc(16 rows x 64 n) += P(16x64) x V(64x128)
#pragma unroll
        for (int kf = 0; kf < 4; kf++) {
            uint32_t Ah[4], Al[4];
            uint32_t a = sb + SPH + (rb * 16 + l15) * 144 + lc * 16 + kf * 32;
            LDSM_X4(Ah, a);
            LDSM_X4(Al, a + 9216);
#pragma unroll
            for (int np = 0; np < 4; np++) {
                uint32_t Bh[4], Bl[4];
                uint32_t va = sb + SVH
                    + (kf * 16 + (bg & 1) * 8 + l7) * 272
                    + ch * 128 + np * 32 + (bg >> 1) * 16;
                LDSM_X4T(Bh, va);
                LDSM_X4T(Bl, va + 17408);
                MMA16816(acc[np*2],   Ah, Bh[0], Bh[1]);
                MMA16816(acc[np*2],   Al, Bh[0], Bh[1]);
                MMA16816(acc[np*2],   Ah, Bl[0], Bl[1]);
                MMA16816(acc[np*2+1], Ah, Bh[2], Bh[3]);
                MMA16816(acc[np*2+1], Al, Bh[2], Bh[3]);
                MMA16816(acc[np*2+1], Ah, Bl[2], Bl[3]);
            }
        }
    }

    // ======================= epilogue: RMSNorm + limb store =======================
#pragma unroll
    for (int nf = 0; nf < 8; nf++)
#pragma unroll
        for (int e = 0; e < 4; e++) acc[nf][e] *= (1.f / 256.f);

    float s1 = 0.f, s2 = 0.f;
#pragma unroll
    for (int nf = 0; nf < 8; nf++) {
        s1 += acc[nf][0] * acc[nf][0] + acc[nf][1] * acc[nf][1];
        s2 += acc[nf][2] * acc[nf][2] + acc[nf][3] * acc[nf][3];
    }
#pragma unroll
    for (int o = 1; o < 4; o <<= 1) {
        s1 += __shfl_xor_sync(0xffffffffu, s1, o);
        s2 += __shfl_xor_sync(0xffffffffu, s2, o);
    }
    __syncthreads();
    if (l3 == 0) {
        fsm[SRED1/4 + r1 * 2 + ch]       = s1;
        fsm[SRED1/4 + (r1 + 8) * 2 + ch] = s2;
    }
    __syncthreads();
    float t1 = fsm[SRED1/4 + r1 * 2] + fsm[SRED1/4 + r1 * 2 + 1];
    float t2 = fsm[SRED1/4 + (r1 + 8) * 2] + fsm[SRED1/4 + (r1 + 8) * 2 + 1];
    float rs1 = rsqrtf(t1 * (1.f / 128.f) + 1e-5f);
    float rs2 = rsqrtf(t2 * (1.f / 128.f) + 1e-5f);

#pragma unroll
    for (int nf = 0; nf < 8; nf++) {
        int cg = ch * 64 + nf * 8 + l3 * 2;
        float2 g = *(const float2*)(gamma + cg);
        int colg = h * 128 + cg;
#pragma unroll
        for (int hh = 0; hh < 2; hh++) {
            float rsv = hh ? rs2 : rs1;
            float v0 = acc[nf][hh*2]     * rsv * g.x;
            float v1 = acc[nf][hh*2 + 1] * rsv * g.y;
            __half h0 = __float2half_rn(v0);
            __half h1 = __float2half_rn(v1);
            __half l0 = __float2half_rn(v0 - __half2float(h0));
            __half l1 = __float2half_rn(v1 - __half2float(h1));
            size_t row = (size_t)(b * Tc + q0 + r1 + hh * 8);
            *(__half2*)(Out2 + row * 2048 + colg) = __halves2half2(h0, h1);
            *(__half2*)(Out2 + qpl + row * 2048 + colg) = __halves2half2(l0, l1);
        }
    }
}

// =====================================================================
extern "C" void kernel_launch(void* const* d_in, const int* in_sizes, int n_in,
                              void* d_out, int out_size)
{
    (void)in_sizes; (void)n_in; (void)out_size;
    const float* x      = (const float*)d_in[0];
    const float* cosb   = (const float*)d_in[1];
    const float* sinb   = (const float*)d_in[2];
    const float* q_w    = (const float*)d_in[3];
    const float* k_w    = (const float*)d_in[4];
    const float* v_w    = (const float*)d_in[5];
    const float* out_w  = (const float*)d_in[6];
    const float* rawmap = (const float*)d_in[7];
    const float* wscale = (const float*)d_in[8];
    const float* gamma  = (const float*)d_in[9];

    float *qp, *kp, *vp;
    __half *x2, *q2, *k2, *v2, *wq2, *wk2, *wv2, *wo2;
    cudaGetSymbolAddress((void**)&qp, g_q);
    cudaGetSymbolAddress((void**)&kp, g_k);
    cudaGetSymbolAddress((void**)&vp, g_v);
    cudaGetSymbolAddress((void**)&x2, g_x2);
    cudaGetSymbolAddress((void**)&q2, g_q2);
    cudaGetSymbolAddress((void**)&k2, g_k2);
    cudaGetSymbolAddress((void**)&v2, g_v2);
    cudaGetSymbolAddress((void**)&wq2, g_wq2);
    cudaGetSymbolAddress((void**)&wk2, g_wk2);
    cudaGetSymbolAddress((void**)&wv2, g_wv2);
    cudaGetSymbolAddress((void**)&wo2, g_wo2);

    cudaFuncSetAttribute(hgemm3,
                         cudaFuncAttributeMaxDynamicSharedMemorySize, G_SMEM);
    cudaFuncSetAttribute(flash_mma,
                         cudaFuncAttributeMaxDynamicSharedMemorySize, FLM_SMEM);

    const size_t xplane = (size_t)BTc * Ec;
    const size_t wqn    = (size_t)Ec * Ec;
    const size_t wkn    = (size_t)KVE * Ec;
    const size_t vplane = (size_t)BTc * KVE;

    // limb splits
    split2_kernel<<<(unsigned)((xplane / 2 + 255) / 256), 256>>>(x, x2, xplane / 2, xplane);
    split2_kernel<<<(unsigned)((wqn / 2 + 255) / 256), 256>>>(q_w, wq2, wqn / 2, wqn);
    split2_kernel<<<(unsigned)((wkn / 2 + 255) / 256), 256>>>(k_w, wk2, wkn / 2, wkn);
    split2_kernel<<<(unsigned)((wkn / 2 + 255) / 256), 256>>>(v_w, wv2, wkn / 2, wkn);
    split2_kernel<<<(unsigned)((wqn / 2 + 255) / 256), 256>>>(out_w, wo2, wqn / 2, wqn);

    // projections (HMMA 3-pass)
    hgemm3<<<dim3(Ec / 128, BTc / 128, 1), 256, G_SMEM>>>(
        x2, xplane, wq2, qp, wq2, qp, Ec, Ec);
    hgemm3<<<dim3(KVE / 128, BTc / 128, 2), 256, G_SMEM>>>(
        x2, xplane, wk2, kp, wv2, vp, KVE, Ec);

    // RoPE + fp16 limb emit; V limb split
    {
        int tq = BTc * (Hc * Mc) * (HDc / 2);
        int tk = BTc * (HKVc * Mc) * (HDc / 2);
        rope_split_kernel<<<(tq + 255) / 256, 256>>>(qp, q2, xplane, cosb, sinb, Hc * Mc);
        rope_split_kernel<<<(tk + 255) / 256, 256>>>(kp, k2, vplane, cosb, sinb, HKVc * Mc);
        split2_kernel<<<(unsigned)((vplane / 2 + 255) / 256), 256>>>(vp, v2, vplane / 2, vplane);
    }

    // tensor-core flash attention + RMSNorm -> x2 limb planes
    flash_mma<<<dim3(Tc / 64, Hc, Bc), 256, FLM_SMEM>>>(
        q2, k2, v2, rawmap, wscale, gamma, x2);

    // output projection
    hgemm3<<<dim3(Ec / 128, BTc / 128, 1), 256, G_SMEM>>>(
        x2, xplane, wo2, (float*)d_out, wo2, (float*)d_out, Ec, Ec);
}